// round 7
// baseline (speedup 1.0000x reference)
#include <cuda_runtime.h>
#include <math.h>

#define BB 8
#define TT 262144
#define CC 8
#define KK 50

// layer kernel tiling: big CTA for 16 warps/SM at 2 CTAs (regs=128 each)
#define NT 256
#define TS 1024
#define TREG 4
#define SH 12  // padded row stride in floats (48B): conflict-free LDS.128

// layer0 tiling
#define NT0 256
#define TS0 2048

// Scratch: ping-pong activation buffers [B][T][C] + normalized weights.
__device__ float g_bufA[(size_t)BB * TT * CC];
__device__ float g_bufB[(size_t)BB * TT * CC];
__device__ float g_w[(size_t)17 * KK * CC * CC];  // [layer][k][o][c], tap-reversed
__device__ float g_w0[CC * KK];                   // [o][k], tap-reversed

// ---------------------------------------------------------------------------
// packed fp32x2 FMA (sm_100+): d = a*b + d elementwise on two f32 lanes
// ---------------------------------------------------------------------------
__device__ __forceinline__ void ffma2(unsigned long long& d,
                                      unsigned long long a,
                                      unsigned long long b) {
    asm("fma.rn.f32x2 %0, %1, %2, %0;" : "+l"(d) : "l"(a), "l"(b));
}

// Fast, overflow-safe tanh/sigmoid (err ~1e-6, tolerance is 1e-3).
__device__ __forceinline__ float fast_tanh(float x) {
    float e2 = __expf(-2.f * fabsf(x));          // in (0,1], never overflows
    float t = __fdividef(1.f - e2, 1.f + e2);
    return copysignf(t, x);
}
__device__ __forceinline__ float fast_sigmoid(float x) {
    return __fdividef(1.f, 1.f + __expf(-x));    // exp->inf gives exact 0 limit
}

// ---------------------------------------------------------------------------
// Weight-norm prep (tap-reversed: lax.conv is cross-correlation, left-pad).
// ---------------------------------------------------------------------------
__global__ void prep_weights(const float* __restrict__ v0,
                             const float* __restrict__ g0,
                             const float* __restrict__ vs,
                             const float* __restrict__ gs) {
    __shared__ float rnorm[CC];
    int l = blockIdx.x;
    int tid = threadIdx.x;
    if (l == 0) {
        if (tid < CC) {
            float s = 0.f;
            for (int k = 0; k < KK; k++) {
                float v = v0[tid * KK + k];
                s += v * v;
            }
            rnorm[tid] = rsqrtf(s);
        }
        __syncthreads();
        for (int idx = tid; idx < CC * KK; idx += blockDim.x) {
            int o = idx / KK, k = idx % KK;
            g_w0[o * KK + k] = g0[o] * v0[o * KK + (KK - 1 - k)] * rnorm[o];
        }
    } else {
        int i = l - 1;
        const float* v = vs + (size_t)i * CC * CC * KK;
        if (tid < CC) {
            float s = 0.f;
            for (int j = 0; j < CC * KK; j++) {
                float x = v[tid * CC * KK + j];
                s += x * x;
            }
            rnorm[tid] = rsqrtf(s);
        }
        __syncthreads();
        float* wout = g_w + (size_t)i * KK * CC * CC;
        for (int idx = tid; idx < KK * CC * CC; idx += blockDim.x) {
            int k = idx / (CC * CC);
            int r = idx % (CC * CC);
            int o = r / CC, c = r % CC;
            wout[idx] = gs[i * CC + o] * v[(o * CC + c) * KK + (KK - 1 - k)] * rnorm[o];
        }
    }
}

// ---------------------------------------------------------------------------
// Layer 0: C_in = 1 (x broadcast), dilation 1. Writes g_bufA [B][T][C].
// ---------------------------------------------------------------------------
__global__ void __launch_bounds__(NT0) layer0_kernel(
    const float* __restrict__ x, const float* __restrict__ b0,
    const float* __restrict__ gw0, const float* __restrict__ gb0) {
    __shared__ float s_x[TS0 + KK];
    __shared__ float s_w[CC * KK];
    __shared__ float s_b[CC], s_gb[CC], s_gw[CC * CC];
    int b = blockIdx.y;
    int t0 = blockIdx.x * TS0;
    int tid = threadIdx.x;
    for (int i = tid; i < CC * KK; i += NT0) s_w[i] = g_w0[i];
    for (int i = tid; i < CC * CC; i += NT0) s_gw[i] = gw0[i];
    if (tid < CC) { s_b[tid] = b0[tid]; s_gb[tid] = gb0[tid]; }
    const float* xb = x + (size_t)b * TT;
    for (int i = tid; i < TS0 + KK - 1; i += NT0) {
        int t = t0 - (KK - 1) + i;
        s_x[i] = (t >= 0) ? xb[t] : 0.f;
    }
    __syncthreads();
    float* hout = g_bufA + (size_t)b * TT * CC;
    for (int p = 0; p < TS0 / NT0; p++) {
        int tl = p * NT0 + tid;
        int j = tl + KK - 1;
        float out[CC];
#pragma unroll
        for (int o = 0; o < CC; o++) out[o] = s_b[o];
#pragma unroll 2
        for (int k = 0; k < KK; k++) {
            float xv = s_x[j - k];
#pragma unroll
            for (int o = 0; o < CC; o++) out[o] += s_w[o * KK + k] * xv;
        }
        float res = s_x[j];
        float h8[CC];
#pragma unroll
        for (int o = 0; o < CC; o++) {
            float g = s_gb[o];
#pragma unroll
            for (int c = 0; c < CC; c++) g += s_gw[o * CC + c] * out[c];
            h8[o] = fast_tanh(out[o]) * fast_sigmoid(g) + res;
        }
        float4* dst = (float4*)(hout + (size_t)(t0 + tl) * CC);
        dst[0] = make_float4(h8[0], h8[1], h8[2], h8[3]);
        dst[1] = make_float4(h8[4], h8[5], h8[6], h8[7]);
    }
}

// ---------------------------------------------------------------------------
// Layers 1..17: fused dilated causal conv (C=8, K=50) + gating + residual.
// v5: R4 inner loop (ptxas-pipelined, 128 regs) with NT=256/TS=1024 so two
// 256-thread CTAs fill the RF exactly -> 16 warps/SM (was 12).
// 48B-padded s_h rows, TREG=4 time blocking, f32x2 channel pairs.
// ---------------------------------------------------------------------------
__global__ void __launch_bounds__(NT, 2) layer_kernel(
    const float* __restrict__ hin, float* __restrict__ hout, int li,
    const float* __restrict__ bias, const float* __restrict__ gw,
    const float* __restrict__ gb, int d) {
    extern __shared__ float smem[];
    float* s_w = smem;               // KK*64  [k][o][c]
    float* s_gw = s_w + KK * 64;     // 64
    float* s_b = s_gw + 64;          // 8
    float* s_gb = s_b + 8;           // 8
    float* s_h = s_gb + 8;           // (TS+halo) rows, stride SH=12 floats

    int halo = 49 * d;
    int tid = threadIdx.x;
    int b = blockIdx.y;
    int t0 = blockIdx.x * TS;

    const float* wsrc = g_w + (size_t)li * KK * 64;
    for (int i = tid; i < KK * 64; i += NT) s_w[i] = wsrc[i];
    for (int i = tid; i < 64; i += NT) s_gw[i] = gw[i];
    if (tid < 8) { s_b[tid] = bias[tid]; s_gb[tid] = gb[tid]; }

    const float* hb = hin + (size_t)b * TT * CC;
    int rows = TS + halo;
    for (int i = tid; i < rows * 2; i += NT) {
        int r = i >> 1, half = i & 1;
        int t = t0 - halo + r;
        float4 v = make_float4(0.f, 0.f, 0.f, 0.f);
        if (t >= 0) v = *(const float4*)(hb + (size_t)t * CC + half * 4);
        *(float4*)(s_h + (size_t)r * SH + half * 4) = v;
    }
    __syncthreads();

    float* ho = hout + (size_t)b * TT * CC;
    int step4 = 3 * d;  // k-step in float4 units (SH/4 * d)

#pragma unroll 1
    for (int p = 0; p < TS / (NT * TREG); p++) {
        int jbase = p * (NT * TREG) + tid + halo;  // row of r=0 output

        unsigned long long acc[TREG][8];
#pragma unroll
        for (int r = 0; r < TREG; r++)
#pragma unroll
            for (int o = 0; o < 8; o++) acc[r][o] = 0ULL;

        const float4* hp[TREG];
#pragma unroll
        for (int r = 0; r < TREG; r++)
            hp[r] = (const float4*)(s_h + (size_t)(jbase + r * NT) * SH);

#pragma unroll 2
        for (int k = 0; k < KK; k++) {
            unsigned long long h[TREG][4];
#pragma unroll
            for (int r = 0; r < TREG; r++) {
                float4 ha = hp[r][0], hc = hp[r][1];
                memcpy(&h[r][0], &ha.x, 8);
                memcpy(&h[r][1], &ha.z, 8);
                memcpy(&h[r][2], &hc.x, 8);
                memcpy(&h[r][3], &hc.z, 8);
            }
            const float4* wk = (const float4*)(s_w + k * 64);
#pragma unroll
            for (int o = 0; o < 8; o++) {
                float4 wa = wk[o * 2], wb = wk[o * 2 + 1];
                unsigned long long w01, w23, w45, w67;
                memcpy(&w01, &wa.x, 8);
                memcpy(&w23, &wa.z, 8);
                memcpy(&w45, &wb.x, 8);
                memcpy(&w67, &wb.z, 8);
#pragma unroll
                for (int r = 0; r < TREG; r++) {
                    ffma2(acc[r][o], h[r][0], w01);
                    ffma2(acc[r][o], h[r][1], w23);
                    ffma2(acc[r][o], h[r][2], w45);
                    ffma2(acc[r][o], h[r][3], w67);
                }
            }
#pragma unroll
            for (int r = 0; r < TREG; r++) hp[r] -= step4;
        }

#pragma unroll
        for (int r = 0; r < TREG; r++) {
            float out[8];
#pragma unroll
            for (int o = 0; o < 8; o++) {
                float2 t2;
                memcpy(&t2, &acc[r][o], 8);
                out[o] = t2.x + t2.y + s_b[o];
            }
            const float4* hres =
                (const float4*)(s_h + (size_t)(jbase + r * NT) * SH);
            float4 ra = hres[0], rb = hres[1];
            float res[8] = {ra.x, ra.y, ra.z, ra.w, rb.x, rb.y, rb.z, rb.w};
            float h8[8];
#pragma unroll
            for (int o = 0; o < 8; o++) {
                float g = s_gb[o];
#pragma unroll
                for (int c = 0; c < 8; c++) g += s_gw[o * 8 + c] * out[c];
                h8[o] = fast_tanh(out[o]) * fast_sigmoid(g) + res[o];
            }
            int tg = t0 + p * (NT * TREG) + r * NT + tid;
            float4* dst = (float4*)(ho + (size_t)tg * CC);
            dst[0] = make_float4(h8[0], h8[1], h8[2], h8[3]);
            dst[1] = make_float4(h8[4], h8[5], h8[6], h8[7]);
        }
    }
}

// ---------------------------------------------------------------------------
// Head: means = mean_w . h + mean_b ; stds = exp(0.5*(lv_w . h + lv_b))
// ---------------------------------------------------------------------------
__global__ void head_kernel(const float* __restrict__ h,
                            const float* __restrict__ mean_w,
                            const float* __restrict__ mean_b,
                            const float* __restrict__ lv_w,
                            const float* __restrict__ lv_b,
                            float* __restrict__ out) {
    __shared__ float s_mw[8], s_lw[8], s_mb, s_lb;
    if (threadIdx.x < 8) {
        s_mw[threadIdx.x] = mean_w[threadIdx.x];
        s_lw[threadIdx.x] = lv_w[threadIdx.x];
    }
    if (threadIdx.x == 0) { s_mb = mean_b[0]; s_lb = lv_b[0]; }
    __syncthreads();
    size_t i = (size_t)blockIdx.x * blockDim.x + threadIdx.x;
    size_t Ntot = (size_t)BB * TT;
    if (i >= Ntot) return;
    const float4* hp = (const float4*)(h + i * 8);
    float4 a = hp[0], b4 = hp[1];
    float m = s_mb + s_mw[0] * a.x + s_mw[1] * a.y + s_mw[2] * a.z +
              s_mw[3] * a.w + s_mw[4] * b4.x + s_mw[5] * b4.y +
              s_mw[6] * b4.z + s_mw[7] * b4.w;
    float lv = s_lb + s_lw[0] * a.x + s_lw[1] * a.y + s_lw[2] * a.z +
               s_lw[3] * a.w + s_lw[4] * b4.x + s_lw[5] * b4.y +
               s_lw[6] * b4.z + s_lw[7] * b4.w;
    out[i] = m;
    out[Ntot + i] = expf(0.5f * lv);
}

// ---------------------------------------------------------------------------
static inline size_t layer_smem(int d) {
    return (size_t)(KK * 64 + 80 + (TS + 49 * d) * SH) * sizeof(float);
}

extern "C" void kernel_launch(void* const* d_in, const int* in_sizes, int n_in,
                              void* d_out, int out_size) {
    const float* x = (const float*)d_in[0];
    const float* v0 = (const float*)d_in[1];
    const float* g0 = (const float*)d_in[2];
    const float* b0 = (const float*)d_in[3];
    const float* gw0 = (const float*)d_in[4];
    const float* gb0 = (const float*)d_in[5];
    const float* vs = (const float*)d_in[6];
    const float* gs = (const float*)d_in[7];
    const float* bs = (const float*)d_in[8];
    const float* gws = (const float*)d_in[9];
    const float* gbs = (const float*)d_in[10];
    const float* mean_w = (const float*)d_in[11];
    const float* mean_b = (const float*)d_in[12];
    const float* lv_w = (const float*)d_in[13];
    const float* lv_b = (const float*)d_in[14];

    float *bufA, *bufB;
    cudaGetSymbolAddress((void**)&bufA, g_bufA);
    cudaGetSymbolAddress((void**)&bufB, g_bufB);

    prep_weights<<<18, 64>>>(v0, g0, vs, gs);

    layer0_kernel<<<dim3(TT / TS0, BB), NT0>>>(x, b0, gw0, gb0);

    static const int DIL[18] = {1, 1, 1, 1, 1, 1, 1, 2, 2, 2, 2, 4, 4, 4, 4, 8, 8, 8};

    cudaFuncSetAttribute(layer_kernel,
                         cudaFuncAttributeMaxDynamicSharedMemorySize,
                         (int)layer_smem(8));

    dim3 grid(TT / TS, BB);
    float* cur = bufA;
    float* nxt = bufB;
    for (int l = 1; l < 18; l++) {
        int d = DIL[l];
        size_t sm = layer_smem(d);
        layer_kernel<<<grid, NT, sm>>>(cur, nxt, l - 1, bs + (l - 1) * 8,
                                       gws + (l - 1) * 64, gbs + (l - 1) * 8, d);
        float* t = cur;
        cur = nxt;
        nxt = t;
    }

    head_kernel<<<(int)(((size_t)BB * TT + 255) / 256), 256>>>(
        cur, mean_w, mean_b, lv_w, lv_b, (float*)d_out);
}

// round 12
// speedup vs baseline: 1.5918x; 1.5918x over previous
#include <cuda_runtime.h>
#include <math.h>

#define BB 8
#define TT 262144
#define CC 8
#define KK 50

#define TS 1024
#define NT 256
#define NT0 256
#define TS0 2048

// Packed bf16 activations: one uint4 = 8 channels. hi/lo split ping-pong.
__device__ uint4 g_hiA[(size_t)BB * TT];
__device__ uint4 g_loA[(size_t)BB * TT];
__device__ uint4 g_hiB[(size_t)BB * TT];
__device__ uint4 g_loB[(size_t)BB * TT];
// Per-lane B fragments: [layer][pair j(25)][lane(32)] = {bh0,bh1,bl0,bl1}
__device__ uint4 g_Bfrag[(size_t)17 * 25 * 32];
__device__ float g_w0[CC * KK];

// ---------------- bf16 via bit ops (no cuda_bf16.h) ------------------------
__device__ __forceinline__ unsigned int f2bf(float x) {
    unsigned int u = __float_as_uint(x);
    return (u + 0x7FFFu + ((u >> 16) & 1u)) >> 16;
}
__device__ __forceinline__ float bf2f(unsigned int b) {
    return __uint_as_float(b << 16);
}
__device__ __forceinline__ unsigned int split_hi(float x, float* resid) {
    unsigned int u = __float_as_uint(x);
    unsigned int r = (u + 0x7FFFu + ((u >> 16) & 1u)) & 0xFFFF0000u;
    *resid = x - __uint_as_float(r);
    return r >> 16;
}
__device__ __forceinline__ void store_hilo(uint4* hi, uint4* lo, size_t row,
                                           const float* h) {
    unsigned int hb[8], lb[8];
#pragma unroll
    for (int c = 0; c < 8; c++) {
        float rs;
        hb[c] = split_hi(h[c], &rs);
        lb[c] = f2bf(rs);
    }
    uint4 H, L;
    H.x = hb[0] | (hb[1] << 16); H.y = hb[2] | (hb[3] << 16);
    H.z = hb[4] | (hb[5] << 16); H.w = hb[6] | (hb[7] << 16);
    L.x = lb[0] | (lb[1] << 16); L.y = lb[2] | (lb[3] << 16);
    L.z = lb[4] | (lb[5] << 16); L.w = lb[6] | (lb[7] << 16);
    hi[row] = H;
    lo[row] = L;
}
__device__ __forceinline__ void load_hilo(uint4 H, uint4 L, float* f) {
    unsigned int hw[4], lw[4];
    hw[0] = H.x; hw[1] = H.y; hw[2] = H.z; hw[3] = H.w;
    lw[0] = L.x; lw[1] = L.y; lw[2] = L.z; lw[3] = L.w;
#pragma unroll
    for (int c = 0; c < 8; c++) {
        unsigned int sh = (c & 1) * 16;
        f[c] = bf2f((hw[c >> 1] >> sh) & 0xFFFFu) +
               bf2f((lw[c >> 1] >> sh) & 0xFFFFu);
    }
}

// ---------------- PTX helpers ----------------------------------------------
__device__ __forceinline__ unsigned int smem_u32(const void* p) {
    unsigned int a;
    asm("{ .reg .u64 t; cvta.to.shared.u64 t, %1; cvt.u32.u64 %0, t; }"
        : "=r"(a) : "l"(p));
    return a;
}
__device__ __forceinline__ void ldmatrix4(unsigned int* a, unsigned int addr) {
    asm volatile(
        "ldmatrix.sync.aligned.m8n8.x4.shared.b16 {%0,%1,%2,%3}, [%4];"
        : "=r"(a[0]), "=r"(a[1]), "=r"(a[2]), "=r"(a[3]) : "r"(addr));
}
__device__ __forceinline__ void mma16816(float* c, const unsigned int* a,
                                         unsigned int b0, unsigned int b1) {
    asm volatile(
        "mma.sync.aligned.m16n8k16.row.col.f32.bf16.bf16.f32 "
        "{%0,%1,%2,%3}, {%4,%5,%6,%7}, {%8,%9}, {%0,%1,%2,%3};"
        : "+f"(c[0]), "+f"(c[1]), "+f"(c[2]), "+f"(c[3])
        : "r"(a[0]), "r"(a[1]), "r"(a[2]), "r"(a[3]), "r"(b0), "r"(b1));
}

__device__ __forceinline__ float fast_tanh(float x) {
    float e2 = __expf(-2.f * fabsf(x));
    float t = __fdividef(1.f - e2, 1.f + e2);
    return copysignf(t, x);
}
__device__ __forceinline__ float fast_sigmoid(float x) {
    return __fdividef(1.f, 1.f + __expf(-x));
}

// ---------------- weight prep ----------------------------------------------
// weight-norm, tap-reverse, hi/lo split, per-lane mma B fragments.
// pair j: A k-cols 0-7 = reversed tap 2j+1, cols 8-15 = reversed tap 2j.
// B frag (m16n8k16, col): lane(gid=lane>>2, tig=lane&3):
//   b0 = {B[2tig][gid], B[2tig+1][gid]}, b1 = {B[2tig+8][gid], B[2tig+9][gid]}
__global__ void prep_weights(const float* __restrict__ v0,
                             const float* __restrict__ g0,
                             const float* __restrict__ vs,
                             const float* __restrict__ gs) {
    __shared__ float rnorm[CC];
    int l = blockIdx.x;
    int tid = threadIdx.x;
    if (l == 0) {
        if (tid < CC) {
            float s = 0.f;
            for (int k = 0; k < KK; k++) {
                float v = v0[tid * KK + k];
                s += v * v;
            }
            rnorm[tid] = rsqrtf(s);
        }
        __syncthreads();
        for (int idx = tid; idx < CC * KK; idx += blockDim.x) {
            int o = idx / KK;
            int k = idx % KK;
            g_w0[o * KK + k] = g0[o] * v0[o * KK + (KK - 1 - k)] * rnorm[o];
        }
    } else {
        int li = l - 1;
        const float* v = vs + (size_t)li * CC * CC * KK;
        if (tid < CC) {
            float s = 0.f;
            for (int j = 0; j < CC * KK; j++) {
                float x = v[tid * CC * KK + j];
                s += x * x;
            }
            rnorm[tid] = rsqrtf(s);
        }
        __syncthreads();
        for (int u = tid; u < 25 * 32; u += blockDim.x) {
            int j = u / 32;
            int lane = u % 32;
            int gid = lane >> 2;
            int tig = lane & 3;
            int krevA = 2 * j + 1;  // k-cols 0-7
            int krevB = 2 * j;      // k-cols 8-15
            int c0 = 2 * tig;
            float gn = gs[li * CC + gid] * rnorm[gid];
            float wA0 = gn * v[(gid * CC + c0) * KK + (KK - 1 - krevA)];
            float wA1 = gn * v[(gid * CC + c0 + 1) * KK + (KK - 1 - krevA)];
            float wB0 = gn * v[(gid * CC + c0) * KK + (KK - 1 - krevB)];
            float wB1 = gn * v[(gid * CC + c0 + 1) * KK + (KK - 1 - krevB)];
            float rA0, rA1, rB0, rB1;
            unsigned int hA0 = split_hi(wA0, &rA0);
            unsigned int hA1 = split_hi(wA1, &rA1);
            unsigned int hB0 = split_hi(wB0, &rB0);
            unsigned int hB1 = split_hi(wB1, &rB1);
            uint4 F;
            F.x = hA0 | (hA1 << 16);            // bh0
            F.y = hB0 | (hB1 << 16);            // bh1
            F.z = f2bf(rA0) | (f2bf(rA1) << 16);  // bl0
            F.w = f2bf(rB0) | (f2bf(rB1) << 16);  // bl1
            g_Bfrag[(size_t)li * 800 + u] = F;
        }
    }
}

// ---------------- layer 0 (C_in=1, fp32) -----------------------------------
__global__ void __launch_bounds__(NT0) layer0_kernel(
    const float* __restrict__ x, const float* __restrict__ b0,
    const float* __restrict__ gw0, const float* __restrict__ gb0) {
    __shared__ float s_x[TS0 + KK];
    __shared__ float s_w[CC * KK];
    __shared__ float s_b[CC], s_gb[CC], s_gw[CC * CC];
    int b = blockIdx.y;
    int t0 = blockIdx.x * TS0;
    int tid = threadIdx.x;
    for (int i = tid; i < CC * KK; i += NT0) s_w[i] = g_w0[i];
    for (int i = tid; i < CC * CC; i += NT0) s_gw[i] = gw0[i];
    if (tid < CC) {
        s_b[tid] = b0[tid];
        s_gb[tid] = gb0[tid];
    }
    const float* xb = x + (size_t)b * TT;
    for (int i = tid; i < TS0 + KK - 1; i += NT0) {
        int t = t0 - (KK - 1) + i;
        s_x[i] = (t >= 0) ? xb[t] : 0.f;
    }
    __syncthreads();
    for (int p = 0; p < TS0 / NT0; p++) {
        int tl = p * NT0 + tid;
        int j = tl + KK - 1;
        float out[CC];
#pragma unroll
        for (int o = 0; o < CC; o++) out[o] = s_b[o];
#pragma unroll 2
        for (int k = 0; k < KK; k++) {
            float xv = s_x[j - k];
#pragma unroll
            for (int o = 0; o < CC; o++) out[o] += s_w[o * KK + k] * xv;
        }
        float res = s_x[j];
        float h8[CC];
#pragma unroll
        for (int o = 0; o < CC; o++) {
            float g = s_gb[o];
#pragma unroll
            for (int c = 0; c < CC; c++) g += s_gw[o * CC + c] * out[c];
            h8[o] = fast_tanh(out[o]) * fast_sigmoid(g) + res;
        }
        store_hilo(g_hiA, g_loA, (size_t)b * TT + t0 + tl, h8);
    }
}

// ---------------- MMA layers 1..17 (mma.sync HMMA bf16x3) -------------------
// smem tile: rows = 16B (8 bf16 ch); 8 consecutive rows = one 8x8 b16 matrix.
// Each warp owns 128 t = 8 m16-tiles; acc[8][4] f32 resident, bias-initialized.
// Per pair j: 1 LDS.128 B frag + per tile {ldmatrix Ah, ldmatrix Al, 3 mma}.
__global__ void __launch_bounds__(NT) mma_layer(
    const uint4* __restrict__ hi_in, const uint4* __restrict__ lo_in,
    uint4* __restrict__ hi_out, uint4* __restrict__ lo_out, int li,
    const float* __restrict__ bias, const float* __restrict__ gw,
    const float* __restrict__ gb, int d) {
    extern __shared__ char smem[];
    int halo = 49 * d;
    int rows = TS + halo;
    float* s_misc = (float*)smem;             // [0..7]=bias [8..71]=gw [72..79]=gb
    uint4* s_Bf = (uint4*)(smem + 512);       // 800 uint4
    uint4* s_hi = (uint4*)(smem + 13312);     // rows
    uint4* s_lo = s_hi + rows;                // rows
    float* s_epi = (float*)(s_lo + rows);     // 8 warps * 128 f32

    int tid = threadIdx.x;
    int wid = tid >> 5;
    int lane = tid & 31;
    int b = blockIdx.y;
    int t0 = blockIdx.x * TS;

    if (tid < 8) s_misc[tid] = bias[tid];
    if (tid >= 32 && tid < 96) s_misc[8 + tid - 32] = gw[tid - 32];
    if (tid >= 96 && tid < 104) s_misc[72 + tid - 96] = gb[tid - 96];

    const uint4* ghi = hi_in + (size_t)b * TT;
    const uint4* glo = lo_in + (size_t)b * TT;
    uint4 z;
    z.x = 0u; z.y = 0u; z.z = 0u; z.w = 0u;
    for (int i = tid; i < rows; i += NT) {
        int t = t0 - halo + i;
        if (t >= 0) {
            s_hi[i] = ghi[t];
            s_lo[i] = glo[t];
        } else {
            s_hi[i] = z;
            s_lo[i] = z;
        }
    }
    const uint4* gBf = g_Bfrag + (size_t)li * 800;
    for (int i = tid; i < 800; i += NT) s_Bf[i] = gBf[i];
    __syncthreads();

    unsigned int base = smem_u32(smem);
    unsigned int hi_a = base + 13312u;
    unsigned int lo_a = hi_a + (unsigned int)rows * 16u;

    // ldmatrix lane mapping: mats {rows0-7,tapA},{rows8-15,tapA},{rows0-7,tapB},
    // {rows8-15,tapB}; tapA = rev tap 2j+1, tapB = rev tap 2j.
    int within = lane & 7;
    int half8 = (lane >> 3) & 1;
    int tapsel = lane >> 4;  // 0 -> shift (2j+1)d, 1 -> shift (2j)d
    int lrow = within + 8 * half8;
    int gid = lane >> 2;
    int tig = lane & 3;

    // warp base row (tile-local 0) in smem rows:
    int wbase = halo + wid * 128;

    float bias_lo = s_misc[2 * tig];
    float bias_hi = s_misc[2 * tig + 1];

    float acc[8][4];
#pragma unroll
    for (int i = 0; i < 8; i++) {
        acc[i][0] = bias_lo;
        acc[i][1] = bias_hi;
        acc[i][2] = bias_lo;
        acc[i][3] = bias_hi;
    }

#pragma unroll 1
    for (int j = 0; j < 25; j++) {
        uint4 Bf = s_Bf[j * 32 + lane];
        int shift = (2 * j + 1 - tapsel) * d;
        unsigned int a0 =
            hi_a + (unsigned int)((wbase + lrow - shift) * 16);
        unsigned int dlo = lo_a - hi_a;
#pragma unroll
        for (int i = 0; i < 8; i++) {
            unsigned int Ah[4], Al[4];
            unsigned int ad = a0 + (unsigned int)(i * 256);  // +16 rows
            ldmatrix4(Ah, ad);
            ldmatrix4(Al, ad + dlo);
            mma16816(acc[i], Ah, Bf.x, Bf.y);
            mma16816(acc[i], Ah, Bf.z, Bf.w);
            mma16816(acc[i], Al, Bf.x, Bf.y);
        }
    }

    // Epilogue: per tile, stage D in smem, one lane per row (lanes 0-15).
    float* epi = s_epi + wid * 128;
    size_t gout = (size_t)b * TT + t0 + wid * 128;
#pragma unroll 1
    for (int i = 0; i < 8; i++) {
        __syncwarp();
        float2* ep2 = (float2*)(epi + gid * 8);
        ep2[tig] = make_float2(acc[i][0], acc[i][1]);
        ep2[tig + 32] = make_float2(acc[i][2], acc[i][3]);
        __syncwarp();
        if (lane < 16) {
            const float4* pr = (const float4*)(epi + lane * 8);
            float4 oa = pr[0], ob = pr[1];
            float out[8] = {oa.x, oa.y, oa.z, oa.w, ob.x, ob.y, ob.z, ob.w};
            int rowg = wbase + i * 16 + lane;
            float hold[8];
            load_hilo(s_hi[rowg], s_lo[rowg], hold);
            float h8[8];
#pragma unroll
            for (int o = 0; o < 8; o++) {
                float g = s_misc[72 + o];
#pragma unroll
                for (int c = 0; c < 8; c++) g += s_misc[8 + o * 8 + c] * out[c];
                h8[o] = fast_tanh(out[o]) * fast_sigmoid(g) + hold[o];
            }
            store_hilo(hi_out, lo_out, gout + i * 16 + lane, h8);
        }
    }
}

// ---------------- head ------------------------------------------------------
__global__ void head_kernel(const uint4* __restrict__ hi,
                            const uint4* __restrict__ lo,
                            const float* __restrict__ mean_w,
                            const float* __restrict__ mean_b,
                            const float* __restrict__ lv_w,
                            const float* __restrict__ lv_b,
                            float* __restrict__ out) {
    __shared__ float s_mw[8], s_lw[8], s_mb, s_lb;
    if (threadIdx.x < 8) {
        s_mw[threadIdx.x] = mean_w[threadIdx.x];
        s_lw[threadIdx.x] = lv_w[threadIdx.x];
    }
    if (threadIdx.x == 0) {
        s_mb = mean_b[0];
        s_lb = lv_b[0];
    }
    __syncthreads();
    size_t i = (size_t)blockIdx.x * blockDim.x + threadIdx.x;
    size_t Ntot = (size_t)BB * TT;
    if (i >= Ntot) return;
    float h[8];
    load_hilo(hi[i], lo[i], h);
    float m = s_mb;
    float lv = s_lb;
#pragma unroll
    for (int c = 0; c < 8; c++) {
        m += s_mw[c] * h[c];
        lv += s_lw[c] * h[c];
    }
    out[i] = m;
    out[Ntot + i] = expf(0.5f * lv);
}

// ---------------------------------------------------------------------------
static size_t mma_smem(int d) {
    int rows = TS + 49 * d;
    return (size_t)13312 + (size_t)rows * 32 + 4096;
}

extern "C" void kernel_launch(void* const* d_in, const int* in_sizes, int n_in,
                              void* d_out, int out_size) {
    const float* x = (const float*)d_in[0];
    const float* v0 = (const float*)d_in[1];
    const float* g0 = (const float*)d_in[2];
    const float* b0 = (const float*)d_in[3];
    const float* gw0 = (const float*)d_in[4];
    const float* gb0 = (const float*)d_in[5];
    const float* vs = (const float*)d_in[6];
    const float* gs = (const float*)d_in[7];
    const float* bs = (const float*)d_in[8];
    const float* gws = (const float*)d_in[9];
    const float* gbs = (const float*)d_in[10];
    const float* mean_w = (const float*)d_in[11];
    const float* mean_b = (const float*)d_in[12];
    const float* lv_w = (const float*)d_in[13];
    const float* lv_b = (const float*)d_in[14];

    uint4* hiA;
    uint4* loA;
    uint4* hiB;
    uint4* loB;
    cudaGetSymbolAddress((void**)&hiA, g_hiA);
    cudaGetSymbolAddress((void**)&loA, g_loA);
    cudaGetSymbolAddress((void**)&hiB, g_hiB);
    cudaGetSymbolAddress((void**)&loB, g_loB);

    prep_weights<<<18, 256>>>(v0, g0, vs, gs);
    layer0_kernel<<<dim3(TT / TS0, BB), NT0>>>(x, b0, gw0, gb0);

    static const int DIL[18] = {1, 1, 1, 1, 1, 1, 1, 2, 2, 2, 2,
                                4, 4, 4, 4, 8, 8, 8};

    cudaFuncSetAttribute(mma_layer, cudaFuncAttributeMaxDynamicSharedMemorySize,
                         (int)mma_smem(8));

    uint4* chi = hiA;
    uint4* clo = loA;
    uint4* nhi = hiB;
    uint4* nlo = loB;
    for (int l = 1; l < 18; l++) {
        int d = DIL[l];
        int li = l - 1;
        mma_layer<<<dim3(TT / TS, BB), NT, mma_smem(d)>>>(
            chi, clo, nhi, nlo, li, bs + li * 8, gws + li * 64, gbs + li * 8, d);
        uint4* th = chi;
        chi = nhi;
        nhi = th;
        uint4* tl = clo;
        clo = nlo;
        nlo = tl;
    }

    head_kernel<<<(int)(((size_t)BB * TT + 255) / 256), 256>>>(
        chi, clo, mean_w, mean_b, lv_w, lv_b, (float*)d_out);
}

// round 13
// speedup vs baseline: 1.6242x; 1.0203x over previous
#include <cuda_runtime.h>
#include <math.h>

#define BB 8
#define TT 262144
#define CC 8
#define KK 50

#define TS 512
#define NT 128
#define NT0 256
#define TS0 2048

// Packed bf16 activations: one uint4 = 8 channels. hi/lo split ping-pong.
__device__ uint4 g_hiA[(size_t)BB * TT];
__device__ uint4 g_loA[(size_t)BB * TT];
__device__ uint4 g_hiB[(size_t)BB * TT];
__device__ uint4 g_loB[(size_t)BB * TT];
// Per-lane B fragments: [layer][pair j(25)][lane(32)] = {bh0,bh1,bl0,bl1}
__device__ uint4 g_Bfrag[(size_t)17 * 25 * 32];
__device__ float g_w0[CC * KK];

// ---------------- bf16 via bit ops (no cuda_bf16.h) ------------------------
__device__ __forceinline__ unsigned int f2bf(float x) {
    unsigned int u = __float_as_uint(x);
    return (u + 0x7FFFu + ((u >> 16) & 1u)) >> 16;
}
__device__ __forceinline__ float bf2f(unsigned int b) {
    return __uint_as_float(b << 16);
}
__device__ __forceinline__ unsigned int split_hi(float x, float* resid) {
    unsigned int u = __float_as_uint(x);
    unsigned int r = (u + 0x7FFFu + ((u >> 16) & 1u)) & 0xFFFF0000u;
    *resid = x - __uint_as_float(r);
    return r >> 16;
}
__device__ __forceinline__ void store_hilo(uint4* hi, uint4* lo, size_t row,
                                           const float* h) {
    unsigned int hb[8], lb[8];
#pragma unroll
    for (int c = 0; c < 8; c++) {
        float rs;
        hb[c] = split_hi(h[c], &rs);
        lb[c] = f2bf(rs);
    }
    uint4 H, L;
    H.x = hb[0] | (hb[1] << 16); H.y = hb[2] | (hb[3] << 16);
    H.z = hb[4] | (hb[5] << 16); H.w = hb[6] | (hb[7] << 16);
    L.x = lb[0] | (lb[1] << 16); L.y = lb[2] | (lb[3] << 16);
    L.z = lb[4] | (lb[5] << 16); L.w = lb[6] | (lb[7] << 16);
    hi[row] = H;
    lo[row] = L;
}
__device__ __forceinline__ void load_hilo(uint4 H, uint4 L, float* f) {
    unsigned int hw[4], lw[4];
    hw[0] = H.x; hw[1] = H.y; hw[2] = H.z; hw[3] = H.w;
    lw[0] = L.x; lw[1] = L.y; lw[2] = L.z; lw[3] = L.w;
#pragma unroll
    for (int c = 0; c < 8; c++) {
        unsigned int sh = (c & 1) * 16;
        f[c] = bf2f((hw[c >> 1] >> sh) & 0xFFFFu) +
               bf2f((lw[c >> 1] >> sh) & 0xFFFFu);
    }
}

// ---------------- PTX helpers ----------------------------------------------
__device__ __forceinline__ unsigned int smem_u32(const void* p) {
    unsigned int a;
    asm("{ .reg .u64 t; cvta.to.shared.u64 t, %1; cvt.u32.u64 %0, t; }"
        : "=r"(a) : "l"(p));
    return a;
}
__device__ __forceinline__ void ldmatrix4(unsigned int* a, unsigned int addr) {
    asm volatile(
        "ldmatrix.sync.aligned.m8n8.x4.shared.b16 {%0,%1,%2,%3}, [%4];"
        : "=r"(a[0]), "=r"(a[1]), "=r"(a[2]), "=r"(a[3]) : "r"(addr));
}
__device__ __forceinline__ void mma16816(float* c, const unsigned int* a,
                                         unsigned int b0, unsigned int b1) {
    asm volatile(
        "mma.sync.aligned.m16n8k16.row.col.f32.bf16.bf16.f32 "
        "{%0,%1,%2,%3}, {%4,%5,%6,%7}, {%8,%9}, {%0,%1,%2,%3};"
        : "+f"(c[0]), "+f"(c[1]), "+f"(c[2]), "+f"(c[3])
        : "r"(a[0]), "r"(a[1]), "r"(a[2]), "r"(a[3]), "r"(b0), "r"(b1));
}

__device__ __forceinline__ float fast_tanh(float x) {
    float e2 = __expf(-2.f * fabsf(x));
    float t = __fdividef(1.f - e2, 1.f + e2);
    return copysignf(t, x);
}
__device__ __forceinline__ float fast_sigmoid(float x) {
    return __fdividef(1.f, 1.f + __expf(-x));
}

// ---------------- weight prep ----------------------------------------------
// weight-norm, tap-reverse, hi/lo split, per-lane mma B fragments.
// pair j: A k-cols 0-7 = reversed tap 2j+1, cols 8-15 = reversed tap 2j.
__global__ void prep_weights(const float* __restrict__ v0,
                             const float* __restrict__ g0,
                             const float* __restrict__ vs,
                             const float* __restrict__ gs) {
    __shared__ float rnorm[CC];
    int l = blockIdx.x;
    int tid = threadIdx.x;
    if (l == 0) {
        if (tid < CC) {
            float s = 0.f;
            for (int k = 0; k < KK; k++) {
                float v = v0[tid * KK + k];
                s += v * v;
            }
            rnorm[tid] = rsqrtf(s);
        }
        __syncthreads();
        for (int idx = tid; idx < CC * KK; idx += blockDim.x) {
            int o = idx / KK;
            int k = idx % KK;
            g_w0[o * KK + k] = g0[o] * v0[o * KK + (KK - 1 - k)] * rnorm[o];
        }
    } else {
        int li = l - 1;
        const float* v = vs + (size_t)li * CC * CC * KK;
        if (tid < CC) {
            float s = 0.f;
            for (int j = 0; j < CC * KK; j++) {
                float x = v[tid * CC * KK + j];
                s += x * x;
            }
            rnorm[tid] = rsqrtf(s);
        }
        __syncthreads();
        for (int u = tid; u < 25 * 32; u += blockDim.x) {
            int j = u / 32;
            int lane = u % 32;
            int gid = lane >> 2;
            int tig = lane & 3;
            int krevA = 2 * j + 1;
            int krevB = 2 * j;
            int c0 = 2 * tig;
            float gn = gs[li * CC + gid] * rnorm[gid];
            float wA0 = gn * v[(gid * CC + c0) * KK + (KK - 1 - krevA)];
            float wA1 = gn * v[(gid * CC + c0 + 1) * KK + (KK - 1 - krevA)];
            float wB0 = gn * v[(gid * CC + c0) * KK + (KK - 1 - krevB)];
            float wB1 = gn * v[(gid * CC + c0 + 1) * KK + (KK - 1 - krevB)];
            float rA0, rA1, rB0, rB1;
            unsigned int hA0 = split_hi(wA0, &rA0);
            unsigned int hA1 = split_hi(wA1, &rA1);
            unsigned int hB0 = split_hi(wB0, &rB0);
            unsigned int hB1 = split_hi(wB1, &rB1);
            uint4 F;
            F.x = hA0 | (hA1 << 16);
            F.y = hB0 | (hB1 << 16);
            F.z = f2bf(rA0) | (f2bf(rA1) << 16);
            F.w = f2bf(rB0) | (f2bf(rB1) << 16);
            g_Bfrag[(size_t)li * 800 + u] = F;
        }
    }
}

// ---------------- layer 0 (C_in=1, fp32) -----------------------------------
__global__ void __launch_bounds__(NT0) layer0_kernel(
    const float* __restrict__ x, const float* __restrict__ b0,
    const float* __restrict__ gw0, const float* __restrict__ gb0) {
    __shared__ float s_x[TS0 + KK];
    __shared__ float s_w[CC * KK];
    __shared__ float s_b[CC], s_gb[CC], s_gw[CC * CC];
    int b = blockIdx.y;
    int t0 = blockIdx.x * TS0;
    int tid = threadIdx.x;
    for (int i = tid; i < CC * KK; i += NT0) s_w[i] = g_w0[i];
    for (int i = tid; i < CC * CC; i += NT0) s_gw[i] = gw0[i];
    if (tid < CC) {
        s_b[tid] = b0[tid];
        s_gb[tid] = gb0[tid];
    }
    const float* xb = x + (size_t)b * TT;
    for (int i = tid; i < TS0 + KK - 1; i += NT0) {
        int t = t0 - (KK - 1) + i;
        s_x[i] = (t >= 0) ? xb[t] : 0.f;
    }
    __syncthreads();
    for (int p = 0; p < TS0 / NT0; p++) {
        int tl = p * NT0 + tid;
        int j = tl + KK - 1;
        float out[CC];
#pragma unroll
        for (int o = 0; o < CC; o++) out[o] = s_b[o];
#pragma unroll 2
        for (int k = 0; k < KK; k++) {
            float xv = s_x[j - k];
#pragma unroll
            for (int o = 0; o < CC; o++) out[o] += s_w[o * KK + k] * xv;
        }
        float res = s_x[j];
        float h8[CC];
#pragma unroll
        for (int o = 0; o < CC; o++) {
            float g = s_gb[o];
#pragma unroll
            for (int c = 0; c < CC; c++) g += s_gw[o * CC + c] * out[c];
            h8[o] = fast_tanh(out[o]) * fast_sigmoid(g) + res;
        }
        store_hilo(g_hiA, g_loA, (size_t)b * TT + t0 + tl, h8);
    }
}

// ---------------- MMA layers 1..17 (mma.sync HMMA bf16x3) -------------------
// v2: NT=128/TS=512 (5-7 CTAs/SM), running addresses in j-loop, 32-lane
// epilogue staging two tiles at once in the (dead) B-frag smem region.
__global__ void __launch_bounds__(NT) mma_layer(
    const uint4* __restrict__ hi_in, const uint4* __restrict__ lo_in,
    uint4* __restrict__ hi_out, uint4* __restrict__ lo_out, int li,
    const float* __restrict__ bias, const float* __restrict__ gw,
    const float* __restrict__ gb, int d) {
    extern __shared__ char smem[];
    int halo = 49 * d;
    int rows = TS + halo;
    float* s_misc = (float*)smem;             // [0..7]=bias [8..71]=gw [72..79]=gb
    uint4* s_Bf = (uint4*)(smem + 512);       // 800 uint4 (dead after mainloop)
    uint4* s_hi = (uint4*)(smem + 13312);     // rows
    uint4* s_lo = s_hi + rows;                // rows

    int tid = threadIdx.x;
    int wid = tid >> 5;
    int lane = tid & 31;
    int b = blockIdx.y;
    int t0 = blockIdx.x * TS;

    if (tid < 8) s_misc[tid] = bias[tid];
    if (tid >= 32 && tid < 96) s_misc[8 + tid - 32] = gw[tid - 32];
    if (tid >= 96 && tid < 104) s_misc[72 + tid - 96] = gb[tid - 96];

    const uint4* ghi = hi_in + (size_t)b * TT;
    const uint4* glo = lo_in + (size_t)b * TT;
    uint4 z;
    z.x = 0u; z.y = 0u; z.z = 0u; z.w = 0u;
    for (int i = tid; i < rows; i += NT) {
        int t = t0 - halo + i;
        if (t >= 0) {
            s_hi[i] = ghi[t];
            s_lo[i] = glo[t];
        } else {
            s_hi[i] = z;
            s_lo[i] = z;
        }
    }
    const uint4* gBf = g_Bfrag + (size_t)li * 800;
    for (int i = tid; i < 800; i += NT) s_Bf[i] = gBf[i];
    __syncthreads();

    unsigned int base = smem_u32(smem);
    unsigned int hi_a = base + 13312u;
    unsigned int dlo = (unsigned int)rows * 16u;

    // ldmatrix lane mapping: lanes 0-15 -> tapA (rev 2j+1), 16-31 -> tapB (2j)
    int within = lane & 7;
    int half8 = (lane >> 3) & 1;
    int tapsel = lane >> 4;
    int lrow = within + 8 * half8;
    int gid = lane >> 2;
    int tig = lane & 3;

    int wbase = halo + wid * 128;

    float bias_lo = s_misc[2 * tig];
    float bias_hi = s_misc[2 * tig + 1];

    float acc[8][4];
#pragma unroll
    for (int i = 0; i < 8; i++) {
        acc[i][0] = bias_lo;
        acc[i][1] = bias_hi;
        acc[i][2] = bias_lo;
        acc[i][3] = bias_hi;
    }

    // running addresses: j=0 shift = (1 - tapsel + 2j)*d rows; -32d bytes per j
    unsigned int aA =
        hi_a + (unsigned int)((wbase + lrow - (1 - tapsel) * d) * 16);
    unsigned int astep = (unsigned int)(32 * d);
    const uint4* bp = s_Bf + lane;

#pragma unroll 1
    for (int j = 0; j < 25; j++) {
        uint4 Bf = *bp;
        bp += 32;
#pragma unroll
        for (int i = 0; i < 8; i++) {
            unsigned int Ah[4], Al[4];
            unsigned int ad = aA + (unsigned int)(i * 256);
            ldmatrix4(Ah, ad);
            ldmatrix4(Al, ad + dlo);
            mma16816(acc[i], Ah, Bf.x, Bf.y);
            mma16816(acc[i], Ah, Bf.z, Bf.w);
            mma16816(acc[i], Al, Bf.x, Bf.y);
        }
        aA -= astep;
    }

    // Mainloop done in all warps before overwriting s_Bf with epilogue stage.
    __syncthreads();

    // Epilogue: stage 2 tiles (32 rows) per pass; all 32 lanes active.
    float* epi = (float*)s_Bf + wid * 256;
    size_t gout = (size_t)b * TT + t0 + wid * 128;
#pragma unroll 1
    for (int i = 0; i < 8; i += 2) {
        __syncwarp();
#pragma unroll
        for (int q = 0; q < 2; q++) {
            float2* e0 = (float2*)(epi + (q * 16 + gid) * 8 + 2 * tig);
            e0[0] = make_float2(acc[i + q][0], acc[i + q][1]);
            float2* e1 = (float2*)(epi + (q * 16 + gid + 8) * 8 + 2 * tig);
            e1[0] = make_float2(acc[i + q][2], acc[i + q][3]);
        }
        __syncwarp();
        {
            const float4* pr = (const float4*)(epi + lane * 8);
            float4 oa = pr[0], ob = pr[1];
            float out[8] = {oa.x, oa.y, oa.z, oa.w, ob.x, ob.y, ob.z, ob.w};
            int rowg = wbase + i * 16 + lane;
            float hold[8];
            load_hilo(s_hi[rowg], s_lo[rowg], hold);
            float h8[8];
#pragma unroll
            for (int o = 0; o < 8; o++) {
                float g = s_misc[72 + o];
#pragma unroll
                for (int c = 0; c < 8; c++) g += s_misc[8 + o * 8 + c] * out[c];
                h8[o] = fast_tanh(out[o]) * fast_sigmoid(g) + hold[o];
            }
            store_hilo(hi_out, lo_out, gout + i * 16 + lane, h8);
        }
    }
}

// ---------------- head ------------------------------------------------------
__global__ void head_kernel(const uint4* __restrict__ hi,
                            const uint4* __restrict__ lo,
                            const float* __restrict__ mean_w,
                            const float* __restrict__ mean_b,
                            const float* __restrict__ lv_w,
                            const float* __restrict__ lv_b,
                            float* __restrict__ out) {
    __shared__ float s_mw[8], s_lw[8], s_mb, s_lb;
    if (threadIdx.x < 8) {
        s_mw[threadIdx.x] = mean_w[threadIdx.x];
        s_lw[threadIdx.x] = lv_w[threadIdx.x];
    }
    if (threadIdx.x == 0) {
        s_mb = mean_b[0];
        s_lb = lv_b[0];
    }
    __syncthreads();
    size_t i = (size_t)blockIdx.x * blockDim.x + threadIdx.x;
    size_t Ntot = (size_t)BB * TT;
    if (i >= Ntot) return;
    float h[8];
    load_hilo(hi[i], lo[i], h);
    float m = s_mb;
    float lv = s_lb;
#pragma unroll
    for (int c = 0; c < 8; c++) {
        m += s_mw[c] * h[c];
        lv += s_lw[c] * h[c];
    }
    out[i] = m;
    out[Ntot + i] = expf(0.5f * lv);
}

// ---------------------------------------------------------------------------
static size_t mma_smem(int d) {
    int rows = TS + 49 * d;
    return (size_t)13312 + (size_t)rows * 32;
}

extern "C" void kernel_launch(void* const* d_in, const int* in_sizes, int n_in,
                              void* d_out, int out_size) {
    const float* x = (const float*)d_in[0];
    const float* v0 = (const float*)d_in[1];
    const float* g0 = (const float*)d_in[2];
    const float* b0 = (const float*)d_in[3];
    const float* gw0 = (const float*)d_in[4];
    const float* gb0 = (const float*)d_in[5];
    const float* vs = (const float*)d_in[6];
    const float* gs = (const float*)d_in[7];
    const float* bs = (const float*)d_in[8];
    const float* gws = (const float*)d_in[9];
    const float* gbs = (const float*)d_in[10];
    const float* mean_w = (const float*)d_in[11];
    const float* mean_b = (const float*)d_in[12];
    const float* lv_w = (const float*)d_in[13];
    const float* lv_b = (const float*)d_in[14];

    uint4* hiA;
    uint4* loA;
    uint4* hiB;
    uint4* loB;
    cudaGetSymbolAddress((void**)&hiA, g_hiA);
    cudaGetSymbolAddress((void**)&loA, g_loA);
    cudaGetSymbolAddress((void**)&hiB, g_hiB);
    cudaGetSymbolAddress((void**)&loB, g_loB);

    prep_weights<<<18, 256>>>(v0, g0, vs, gs);
    layer0_kernel<<<dim3(TT / TS0, BB), NT0>>>(x, b0, gw0, gb0);

    static const int DIL[18] = {1, 1, 1, 1, 1, 1, 1, 2, 2, 2, 2,
                                4, 4, 4, 4, 8, 8, 8};

    cudaFuncSetAttribute(mma_layer, cudaFuncAttributeMaxDynamicSharedMemorySize,
                         (int)mma_smem(8));

    uint4* chi = hiA;
    uint4* clo = loA;
    uint4* nhi = hiB;
    uint4* nlo = loB;
    for (int l = 1; l < 18; l++) {
        int d = DIL[l];
        int li = l - 1;
        mma_layer<<<dim3(TT / TS, BB), NT, mma_smem(d)>>>(
            chi, clo, nhi, nlo, li, bs + li * 8, gws + li * 64, gbs + li * 8, d);
        uint4* th = chi;
        chi = nhi;
        nhi = th;
        uint4* tl = clo;
        clo = nlo;
        nlo = tl;
    }

    head_kernel<<<(int)(((size_t)BB * TT + 255) / 256), 256>>>(
        chi, clo, mean_w, mean_b, lv_w, lv_b, (float*)d_out);
}